// round 12
// baseline (speedup 1.0000x reference)
#include <cuda_runtime.h>
#include <cuda_fp16.h>
#include <cstdint>

// ---------------------------------------------------------------------------
// Problem constants
// ---------------------------------------------------------------------------
#define BATCH        2048
#define IN_FEAT      4096
#define OUT_FEAT     4096
#define BLOCK        32
#define NNZ          2048
#define N_ROW_BLOCKS 128
#define MTILE        256                    // batch rows per CTA (4 warps x 64)
#define N_BATCH_TILES (BATCH / MTILE)       // 8
#define N_CHUNKS     (NNZ / 32)             // 64

// ---------------------------------------------------------------------------
// Device scratch (__device__ globals only; no runtime allocation)
// ---------------------------------------------------------------------------
__device__ __align__(256) __half g_xh[BATCH * IN_FEAT];     // 16 MB
__device__ __align__(256) __half g_wh[NNZ * BLOCK * BLOCK]; // 4 MB
__device__ int g_hist[N_CHUNKS * N_ROW_BLOCKS];   // per-chunk row histogram
__device__ int g_base[N_CHUNKS * N_ROW_BLOCKS];   // per-chunk scatter bases
__device__ int g_cnt[N_ROW_BLOCKS];
__device__ int g_off[N_ROW_BLOCKS];
__device__ int g_order[N_ROW_BLOCKS];   // row-blocks sorted by cnt desc
__device__ int g_list[NNZ];             // packed: (col << 16) | nnz_index

// ---------------------------------------------------------------------------
// Helpers
// ---------------------------------------------------------------------------
__device__ __forceinline__ uint32_t smem_u32(const void* p) {
    uint32_t a;
    asm("{ .reg .u64 t; cvta.to.shared.u64 t, %1; cvt.u32.u64 %0, t; }"
        : "=r"(a) : "l"(p));
    return a;
}

// SW64 swizzle for 64B-pitch rows: XOR bits [5:4] with bits [9:8].
#define SW64(o) ((o) ^ (((o) >> 3) & 0x30))

#define CP_ASYNC16(dst, src) \
    asm volatile("cp.async.cg.shared.global [%0], [%1], 16;" \
                 :: "r"(dst), "l"(src) : "memory")
#define CP_COMMIT() asm volatile("cp.async.commit_group;" ::: "memory")
#define CP_WAIT1()  asm volatile("cp.async.wait_group 1;" ::: "memory")

__device__ __forceinline__ void ldsm_x4(uint32_t* r, uint32_t addr) {
    asm volatile("ldmatrix.sync.aligned.m8n8.x4.shared.b16 {%0,%1,%2,%3}, [%4];"
                 : "=r"(r[0]), "=r"(r[1]), "=r"(r[2]), "=r"(r[3])
                 : "r"(addr));
}

__device__ __forceinline__ void mma_16816(float* d, const uint32_t* a,
                                          const uint32_t* b) {
    asm volatile(
        "mma.sync.aligned.m16n8k16.row.col.f32.f16.f16.f32 "
        "{%0,%1,%2,%3}, {%4,%5,%6,%7}, {%8,%9}, {%0,%1,%2,%3};"
        : "+f"(d[0]), "+f"(d[1]), "+f"(d[2]), "+f"(d[3])
        : "r"(a[0]), "r"(a[1]), "r"(a[2]), "r"(a[3]), "r"(b[0]), "r"(b[1]));
}

// ---------------------------------------------------------------------------
// Kernel 1: fused fp32->fp16 conversion (x, w) + complete CSR build.
// Grid: 8192 x-blocks + 2048 w-blocks + 1 CSR block, 256 threads each.
// ---------------------------------------------------------------------------
#define X_F4_BLOCKS 8192
#define W_F4_BLOCKS 2048

__device__ __forceinline__ void csr_build_block(const int* __restrict__ rows,
                                                const int* __restrict__ cols) {
    const int t   = threadIdx.x;           // 0..255
    const int wrp = t >> 5;                // 0..7
    const int lid = t & 31;

    // ---- phase 0: zero histogram (8192 ints, 32 per thread) ----
#pragma unroll
    for (int i = 0; i < 32; i++) g_hist[i * 256 + t] = 0;
    __syncthreads();

    // ---- phase 1: per-chunk histogram via match_any (8 chunks per warp) ----
#pragma unroll
    for (int p = 0; p < 8; p++) {
        int c = p * 8 + wrp;               // chunk 0..63
        int n = c * 32 + lid;
        int row = rows[n];
        unsigned m = __match_any_sync(0xffffffffu, row);
        int rank = __popc(m & ((1u << lid) - 1));
        if (rank == 0) g_hist[c * N_ROW_BLOCKS + row] = __popc(m);
    }
    __syncthreads();

    // ---- phase 2: totals, offsets, longest-first order, chunk bases ----
    if (t < N_ROW_BLOCKS) {
        int sum = 0;
#pragma unroll 8
        for (int c = 0; c < N_CHUNKS; c++) sum += g_hist[c * N_ROW_BLOCKS + t];
        g_cnt[t] = sum;
    }
    __syncthreads();
    if (t < N_ROW_BLOCKS) {
        const int cnt = g_cnt[t];
        int off = 0, rank = 0;
#pragma unroll 8
        for (int i = 0; i < N_ROW_BLOCKS; i++) {
            int ci = g_cnt[i];
            off  += (i < t) ? ci : 0;
            rank += (ci > cnt) || (ci == cnt && i < t);
        }
        g_off[t] = off;
        g_order[rank] = t;
        int run = off;
#pragma unroll 8
        for (int c = 0; c < N_CHUNKS; c++) {
            g_base[c * N_ROW_BLOCKS + t] = run;
            run += g_hist[c * N_ROW_BLOCKS + t];
        }
    }
    __syncthreads();

    // ---- phase 3: scatter (chunk = pass*8 + warp, lane order == n order) ----
#pragma unroll
    for (int p = 0; p < 8; p++) {
        int n = p * 256 + t;
        int row = rows[n];
        int chunk = n >> 5;                // == p*8 + wrp
        unsigned m = __match_any_sync(0xffffffffu, row);
        int rank = __popc(m & ((1u << lid) - 1));
        g_list[g_base[chunk * N_ROW_BLOCKS + row] + rank] = (cols[n] << 16) | n;
    }
}

__global__ void __launch_bounds__(256)
cvt_csr_kernel(const float* __restrict__ x, const float* __restrict__ w,
               const int* __restrict__ rows, const int* __restrict__ cols) {
    int b = blockIdx.x;
    if (b < X_F4_BLOCKS) {
        int i = b * 256 + threadIdx.x;
        float4 v = reinterpret_cast<const float4*>(x)[i];
        __half2* d = reinterpret_cast<__half2*>(g_xh);
        d[2 * i]     = __floats2half2_rn(v.x, v.y);
        d[2 * i + 1] = __floats2half2_rn(v.z, v.w);
    } else if (b < X_F4_BLOCKS + W_F4_BLOCKS) {
        int i = (b - X_F4_BLOCKS) * 256 + threadIdx.x;
        float4 v = reinterpret_cast<const float4*>(w)[i];
        __half2* d = reinterpret_cast<__half2*>(g_wh);
        d[2 * i]     = __floats2half2_rn(v.x, v.y);
        d[2 * i + 1] = __floats2half2_rn(v.z, v.w);
    } else {
        csr_build_block(rows, cols);
    }
}

// ---------------------------------------------------------------------------
// Kernel 2: main block-sparse GEMM, CTA tile 256x32 (4 warps x 64 rows).
// Grid (128 row-blocks via g_order, 8 batch-tiles), 128 threads.
// Per iter: A 16KB unique + B 2KB (x4 warp reads); one barrier covers 2x the
// work of the R10 config; w L2 traffic halves. 64B-pitch SW64 tiles, 3 stages
// (54KB dynamic SMEM -> 4 CTAs/SM, 16 warps), wait_group 1.
// ---------------------------------------------------------------------------
#define A_BYTES     (MTILE * 64)           // 16384 per stage
#define B_BYTES     (BLOCK * 64)           // 2048 per stage
#define STAGE_BYTES (A_BYTES + B_BYTES)    // 18432
#define STAGES      3
#define SMEM_DYN    (STAGES * STAGE_BYTES) // 55296
#define CTA_THREADS 128

__device__ __forceinline__ void issue_loads(uint32_t sA, uint32_t sB,
                                            int tid, int batch0, int packed) {
    const int c   = packed >> 16;
    const int idx = packed & 0xffff;
    // A: 256 rows x 4 segs = 1024 x 16B ops over 128 threads (8 each).
#pragma unroll
    for (int i = 0; i < 8; i++) {
        int f = i * 128 + tid;
        int row = f >> 2, seg = f & 3;
        const char* src = reinterpret_cast<const char*>(
            g_xh + (size_t)(batch0 + row) * IN_FEAT + c * BLOCK + seg * 8);
        CP_ASYNC16(sA + SW64((uint32_t)row * 64 + seg * 16), src);
    }
    // B: 32 rows x 4 segs = 128 x 16B ops over 128 threads (1 each).
    {
        int wr = tid >> 2, wi = tid & 3;
        const char* src = reinterpret_cast<const char*>(
            g_wh + (size_t)idx * (BLOCK * BLOCK) + wr * BLOCK + wi * 8);
        CP_ASYNC16(sB + SW64((uint32_t)wr * 64 + wi * 16), src);
    }
}

__global__ void __launch_bounds__(CTA_THREADS)
bsd_main_kernel(float* __restrict__ out) {
    extern __shared__ __align__(1024) char sbuf[];

    const int r      = g_order[blockIdx.x];
    const int batch0 = blockIdx.y * MTILE;
    const int tid = threadIdx.x;
    const int wid = tid >> 5;          // 0..3
    const int lid = tid & 31;
    const int mbase = wid * 64;        // warp owns 64 batch rows

    const uint32_t sb = smem_u32(sbuf);
    const int cnt = g_cnt[r];
    const int off = g_off[r];

    float acc[4][4][4];
#pragma unroll
    for (int mi = 0; mi < 4; mi++)
#pragma unroll
        for (int nj = 0; nj < 4; nj++)
#pragma unroll
            for (int k = 0; k < 4; k++) acc[mi][nj][k] = 0.f;

    // Prologue: issue blocks 0 and 1 into stages 0 and 1 (commit always).
    if (cnt > 0) issue_loads(sb, sb + A_BYTES, tid, batch0, g_list[off]);
    CP_COMMIT();
    if (cnt > 1) issue_loads(sb + STAGE_BYTES, sb + STAGE_BYTES + A_BYTES,
                             tid, batch0, g_list[off + 1]);
    CP_COMMIT();

    // Mainloop, one barrier per iteration:
    //  WAIT1  -> block `it` landed (<=1 group pending after it)
    //  sync   -> visibility of stage it%3 + all reads of stage (it-1)%3 done
    //  issue block it+2 into stage (it+2)%3 == (it-1)%3
    //  ldmatrix + MMA on stage it%3
    for (int it = 0; it < cnt; ++it) {
        CP_WAIT1();
        __syncthreads();

        const int j = it + STAGES - 1;
        const uint32_t sw = sb + ((uint32_t)(j % STAGES)) * STAGE_BYTES;
        if (j < cnt)
            issue_loads(sw, sw + A_BYTES, tid, batch0, g_list[off + j]);
        CP_COMMIT();

        const uint32_t sA = sb + ((uint32_t)(it % STAGES)) * STAGE_BYTES;
        const uint32_t sB = sA + A_BYTES;

        // B fragments once per iteration (shared across all 4 mi sub-tiles).
        uint32_t bf[2][4][2];
#pragma unroll
        for (int ki = 0; ki < 2; ki++)
#pragma unroll
            for (int p = 0; p < 2; p++) {
                uint32_t n  = (uint32_t)(p * 16 + ((lid >> 4) * 8) + (lid & 7));
                uint32_t kb = (uint32_t)(ki * 32 + (((lid >> 3) & 1) * 16));
                uint32_t tt[4];
                ldsm_x4(tt, sB + SW64(n * 64 + kb));
                bf[ki][2 * p + 0][0] = tt[0];
                bf[ki][2 * p + 0][1] = tt[1];
                bf[ki][2 * p + 1][0] = tt[2];
                bf[ki][2 * p + 1][1] = tt[3];
            }

        // A fragments loaded per mi (keeps only 8 af regs live).
#pragma unroll
        for (int mi = 0; mi < 4; mi++) {
            uint32_t af[2][4];
#pragma unroll
            for (int ki = 0; ki < 2; ki++) {
                uint32_t row = (uint32_t)(mbase + mi * 16 + (lid & 15));
                uint32_t kb  = (uint32_t)(ki * 32 + ((lid >> 4) * 16));
                ldsm_x4(af[ki], sA + SW64(row * 64 + kb));
            }
#pragma unroll
            for (int nj = 0; nj < 4; nj++)
#pragma unroll
                for (int ki = 0; ki < 2; ki++)
                    mma_16816(acc[mi][nj], af[ki], bf[ki][nj]);
        }
    }

    // Epilogue: D fragment layout -> global (zeros if row-block empty).
    const int g = lid >> 2, t4 = lid & 3;
#pragma unroll
    for (int mi = 0; mi < 4; mi++) {
#pragma unroll
        for (int nj = 0; nj < 4; nj++) {
            const int row = batch0 + mbase + mi * 16 + g;
            const int col = r * BLOCK + nj * 8 + 2 * t4;
            float2* p0 = reinterpret_cast<float2*>(out + (size_t)row * OUT_FEAT + col);
            float2* p1 = reinterpret_cast<float2*>(out + (size_t)(row + 8) * OUT_FEAT + col);
            *p0 = make_float2(acc[mi][nj][0], acc[mi][nj][1]);
            *p1 = make_float2(acc[mi][nj][2], acc[mi][nj][3]);
        }
    }
}

// ---------------------------------------------------------------------------
// Launch (2 kernels)
// ---------------------------------------------------------------------------
extern "C" void kernel_launch(void* const* d_in, const int* in_sizes, int n_in,
                              void* d_out, int out_size) {
    (void)in_sizes; (void)n_in; (void)out_size;
    const float* x    = (const float*)d_in[0];   // [2048, 4096] fp32
    const float* w    = (const float*)d_in[1];   // [2048, 32, 32] fp32
    const int*   rows = (const int*)d_in[2];     // [2048] int32
    const int*   cols = (const int*)d_in[3];     // [2048] int32
    float*       out  = (float*)d_out;           // [2048, 4096] fp32

    cudaFuncSetAttribute(bsd_main_kernel,
                         cudaFuncAttributeMaxDynamicSharedMemorySize, SMEM_DYN);

    cvt_csr_kernel<<<X_F4_BLOCKS + W_F4_BLOCKS + 1, 256>>>(x, w, rows, cols);

    dim3 grid(N_ROW_BLOCKS, N_BATCH_TILES);
    bsd_main_kernel<<<grid, CTA_THREADS, SMEM_DYN>>>(out);
}

// round 13
// speedup vs baseline: 1.0257x; 1.0257x over previous
#include <cuda_runtime.h>
#include <cuda_fp16.h>
#include <cstdint>

// ---------------------------------------------------------------------------
// Problem constants
// ---------------------------------------------------------------------------
#define BATCH        2048
#define IN_FEAT      4096
#define OUT_FEAT     4096
#define BLOCK        32
#define NNZ          2048
#define N_ROW_BLOCKS 128
#define MTILE        128                    // batch rows per CTA (2 warps x 64)
#define N_BATCH_TILES (BATCH / MTILE)       // 16
#define N_CHUNKS     (NNZ / 32)             // 64

// ---------------------------------------------------------------------------
// Device scratch (__device__ globals only; no runtime allocation)
// ---------------------------------------------------------------------------
__device__ __align__(256) __half g_xh[BATCH * IN_FEAT];     // 16 MB
__device__ __align__(256) __half g_wh[NNZ * BLOCK * BLOCK]; // 4 MB
__device__ int g_hist[N_CHUNKS * N_ROW_BLOCKS];   // per-chunk row histogram
__device__ int g_base[N_CHUNKS * N_ROW_BLOCKS];   // per-chunk scatter bases
__device__ int g_cnt[N_ROW_BLOCKS];
__device__ int g_off[N_ROW_BLOCKS];
__device__ int g_order[N_ROW_BLOCKS];   // row-blocks sorted by cnt desc
__device__ int g_list[NNZ];             // packed: (col << 16) | nnz_index

// ---------------------------------------------------------------------------
// Helpers
// ---------------------------------------------------------------------------
__device__ __forceinline__ uint32_t smem_u32(const void* p) {
    uint32_t a;
    asm("{ .reg .u64 t; cvta.to.shared.u64 t, %1; cvt.u32.u64 %0, t; }"
        : "=r"(a) : "l"(p));
    return a;
}

// SW64 swizzle for 64B-pitch rows: XOR bits [5:4] with bits [9:8].
#define SW64(o) ((o) ^ (((o) >> 3) & 0x30))

#define CP_ASYNC16(dst, src) \
    asm volatile("cp.async.cg.shared.global [%0], [%1], 16;" \
                 :: "r"(dst), "l"(src) : "memory")
#define CP_COMMIT() asm volatile("cp.async.commit_group;" ::: "memory")
#define CP_WAIT1()  asm volatile("cp.async.wait_group 1;" ::: "memory")

__device__ __forceinline__ void ldsm_x4(uint32_t* r, uint32_t addr) {
    asm volatile("ldmatrix.sync.aligned.m8n8.x4.shared.b16 {%0,%1,%2,%3}, [%4];"
                 : "=r"(r[0]), "=r"(r[1]), "=r"(r[2]), "=r"(r[3])
                 : "r"(addr));
}

__device__ __forceinline__ void mma_16816(float* d, const uint32_t* a,
                                          const uint32_t* b) {
    asm volatile(
        "mma.sync.aligned.m16n8k16.row.col.f32.f16.f16.f32 "
        "{%0,%1,%2,%3}, {%4,%5,%6,%7}, {%8,%9}, {%0,%1,%2,%3};"
        : "+f"(d[0]), "+f"(d[1]), "+f"(d[2]), "+f"(d[3])
        : "r"(a[0]), "r"(a[1]), "r"(a[2]), "r"(a[3]), "r"(b[0]), "r"(b[1]));
}

// ---------------------------------------------------------------------------
// Kernel 1: fused fp32->fp16 conversion (x, w) + complete CSR build.
// Grid: 8192 x-blocks + 2048 w-blocks + 1 CSR block, 256 threads each.
// ---------------------------------------------------------------------------
#define X_F4_BLOCKS 8192
#define W_F4_BLOCKS 2048

__device__ __forceinline__ void csr_build_block(const int* __restrict__ rows,
                                                const int* __restrict__ cols) {
    const int t   = threadIdx.x;           // 0..255
    const int wrp = t >> 5;                // 0..7
    const int lid = t & 31;

    // ---- phase 0: zero histogram (8192 ints, 32 per thread) ----
#pragma unroll
    for (int i = 0; i < 32; i++) g_hist[i * 256 + t] = 0;
    __syncthreads();

    // ---- phase 1: per-chunk histogram via match_any (8 chunks per warp) ----
#pragma unroll
    for (int p = 0; p < 8; p++) {
        int c = p * 8 + wrp;               // chunk 0..63
        int n = c * 32 + lid;
        int row = rows[n];
        unsigned m = __match_any_sync(0xffffffffu, row);
        int rank = __popc(m & ((1u << lid) - 1));
        if (rank == 0) g_hist[c * N_ROW_BLOCKS + row] = __popc(m);
    }
    __syncthreads();

    // ---- phase 2: totals, offsets, longest-first order, chunk bases ----
    if (t < N_ROW_BLOCKS) {
        int sum = 0;
#pragma unroll 8
        for (int c = 0; c < N_CHUNKS; c++) sum += g_hist[c * N_ROW_BLOCKS + t];
        g_cnt[t] = sum;
    }
    __syncthreads();
    if (t < N_ROW_BLOCKS) {
        const int cnt = g_cnt[t];
        int off = 0, rank = 0;
#pragma unroll 8
        for (int i = 0; i < N_ROW_BLOCKS; i++) {
            int ci = g_cnt[i];
            off  += (i < t) ? ci : 0;
            rank += (ci > cnt) || (ci == cnt && i < t);
        }
        g_off[t] = off;
        g_order[rank] = t;
        int run = off;
#pragma unroll 8
        for (int c = 0; c < N_CHUNKS; c++) {
            g_base[c * N_ROW_BLOCKS + t] = run;
            run += g_hist[c * N_ROW_BLOCKS + t];
        }
    }
    __syncthreads();

    // ---- phase 3: scatter (chunk = pass*8 + warp, lane order == n order) ----
#pragma unroll
    for (int p = 0; p < 8; p++) {
        int n = p * 256 + t;
        int row = rows[n];
        int chunk = n >> 5;                // == p*8 + wrp
        unsigned m = __match_any_sync(0xffffffffu, row);
        int rank = __popc(m & ((1u << lid) - 1));
        g_list[g_base[chunk * N_ROW_BLOCKS + row] + rank] = (cols[n] << 16) | n;
    }
}

__global__ void __launch_bounds__(256)
cvt_csr_kernel(const float* __restrict__ x, const float* __restrict__ w,
               const int* __restrict__ rows, const int* __restrict__ cols) {
    int b = blockIdx.x;
    if (b < X_F4_BLOCKS) {
        int i = b * 256 + threadIdx.x;
        float4 v = reinterpret_cast<const float4*>(x)[i];
        __half2* d = reinterpret_cast<__half2*>(g_xh);
        d[2 * i]     = __floats2half2_rn(v.x, v.y);
        d[2 * i + 1] = __floats2half2_rn(v.z, v.w);
    } else if (b < X_F4_BLOCKS + W_F4_BLOCKS) {
        int i = (b - X_F4_BLOCKS) * 256 + threadIdx.x;
        float4 v = reinterpret_cast<const float4*>(w)[i];
        __half2* d = reinterpret_cast<__half2*>(g_wh);
        d[2 * i]     = __floats2half2_rn(v.x, v.y);
        d[2 * i + 1] = __floats2half2_rn(v.z, v.w);
    } else {
        csr_build_block(rows, cols);
    }
}

// ---------------------------------------------------------------------------
// Kernel 2: main block-sparse GEMM, warp tile 64x32 (R10 shape).
// Grid (128 row-blocks via g_order, 16 batch-tiles), 64 threads (2 warps).
// 3 stages x 10KB static SMEM -> 6 CTAs/SM. ILP change vs R10: ALL 12
// ldmatrix ops (B + all 4 mi A-frags) issue back-to-back after the barrier,
// overlapping their latencies once, then the 32 MMAs run against register
// fragments. ~150 regs; 6-CTA reg budget at 64 threads is 170 -> no cap.
// ---------------------------------------------------------------------------
#define A_BYTES     (MTILE * 64)           // 8192 per stage
#define B_BYTES     (BLOCK * 64)           // 2048 per stage
#define STAGE_BYTES (A_BYTES + B_BYTES)    // 10240
#define STAGES      3
#define CTA_THREADS 64

__device__ __forceinline__ void issue_loads(uint32_t sA, uint32_t sB,
                                            int tid, int batch0, int packed) {
    const int c   = packed >> 16;
    const int idx = packed & 0xffff;
    // A: 128 rows x 4 segs = 512 x 16B ops over 64 threads (8 each).
#pragma unroll
    for (int i = 0; i < 8; i++) {
        int f = i * 64 + tid;
        int row = f >> 2, seg = f & 3;
        const char* src = reinterpret_cast<const char*>(
            g_xh + (size_t)(batch0 + row) * IN_FEAT + c * BLOCK + seg * 8);
        CP_ASYNC16(sA + SW64((uint32_t)row * 64 + seg * 16), src);
    }
    // B: 32 rows x 4 segs = 128 x 16B ops over 64 threads (2 each).
#pragma unroll
    for (int i = 0; i < 2; i++) {
        int f = i * 64 + tid;
        int wr = f >> 2, wi = f & 3;
        const char* src = reinterpret_cast<const char*>(
            g_wh + (size_t)idx * (BLOCK * BLOCK) + wr * BLOCK + wi * 8);
        CP_ASYNC16(sB + SW64((uint32_t)wr * 64 + wi * 16), src);
    }
}

__global__ void __launch_bounds__(CTA_THREADS)
bsd_main_kernel(float* __restrict__ out) {
    __shared__ __align__(1024) char sbuf[STAGES * STAGE_BYTES];   // 30720 B

    const int r      = g_order[blockIdx.x];
    const int batch0 = blockIdx.y * MTILE;
    const int tid = threadIdx.x;
    const int wid = tid >> 5;          // 0..1
    const int lid = tid & 31;
    const int mbase = wid * 64;        // warp owns 64 batch rows

    const uint32_t sb = smem_u32(sbuf);
    const int cnt = g_cnt[r];
    const int off = g_off[r];

    float acc[4][4][4];
#pragma unroll
    for (int mi = 0; mi < 4; mi++)
#pragma unroll
        for (int nj = 0; nj < 4; nj++)
#pragma unroll
            for (int k = 0; k < 4; k++) acc[mi][nj][k] = 0.f;

    // Prologue: issue blocks 0 and 1 into stages 0 and 1 (commit always).
    if (cnt > 0) issue_loads(sb, sb + A_BYTES, tid, batch0, g_list[off]);
    CP_COMMIT();
    if (cnt > 1) issue_loads(sb + STAGE_BYTES, sb + STAGE_BYTES + A_BYTES,
                             tid, batch0, g_list[off + 1]);
    CP_COMMIT();

    // Mainloop, one barrier per iteration:
    //  WAIT1  -> block `it` landed (<=1 group pending after it)
    //  sync   -> visibility of stage it%3 + all reads of stage (it-1)%3 done
    //  issue block it+2 into stage (it+2)%3 == (it-1)%3
    //  ALL 12 ldmatrix up front (latencies overlap), then 32 MMAs
    for (int it = 0; it < cnt; ++it) {
        CP_WAIT1();
        __syncthreads();

        const int j = it + STAGES - 1;
        const uint32_t sw = sb + ((uint32_t)(j % STAGES)) * STAGE_BYTES;
        if (j < cnt)
            issue_loads(sw, sw + A_BYTES, tid, batch0, g_list[off + j]);
        CP_COMMIT();

        const uint32_t sA = sb + ((uint32_t)(it % STAGES)) * STAGE_BYTES;
        const uint32_t sB = sA + A_BYTES;

        // ---- issue every fragment load back-to-back ----
        uint32_t bf[2][4][2];
#pragma unroll
        for (int ki = 0; ki < 2; ki++)
#pragma unroll
            for (int p = 0; p < 2; p++) {
                uint32_t n  = (uint32_t)(p * 16 + ((lid >> 4) * 8) + (lid & 7));
                uint32_t kb = (uint32_t)(ki * 32 + (((lid >> 3) & 1) * 16));
                uint32_t tt[4];
                ldsm_x4(tt, sB + SW64(n * 64 + kb));
                bf[ki][2 * p + 0][0] = tt[0];
                bf[ki][2 * p + 0][1] = tt[1];
                bf[ki][2 * p + 1][0] = tt[2];
                bf[ki][2 * p + 1][1] = tt[3];
            }
        uint32_t af[4][2][4];
#pragma unroll
        for (int mi = 0; mi < 4; mi++)
#pragma unroll
            for (int ki = 0; ki < 2; ki++) {
                uint32_t row = (uint32_t)(mbase + mi * 16 + (lid & 15));
                uint32_t kb  = (uint32_t)(ki * 32 + ((lid >> 4) * 16));
                ldsm_x4(af[mi][ki], sA + SW64(row * 64 + kb));
            }

        // ---- 32 MMAs against register fragments ----
#pragma unroll
        for (int mi = 0; mi < 4; mi++)
#pragma unroll
            for (int nj = 0; nj < 4; nj++)
#pragma unroll
                for (int ki = 0; ki < 2; ki++)
                    mma_16816(acc[mi][nj], af[mi][ki], bf[ki][nj]);
    }

    // Epilogue: D fragment layout -> global (zeros if row-block empty).
    const int g = lid >> 2, t4 = lid & 3;
#pragma unroll
    for (int mi = 0; mi < 4; mi++) {
#pragma unroll
        for (int nj = 0; nj < 4; nj++) {
            const int row = batch0 + mbase + mi * 16 + g;
            const int col = r * BLOCK + nj * 8 + 2 * t4;
            float2* p0 = reinterpret_cast<float2*>(out + (size_t)row * OUT_FEAT + col);
            float2* p1 = reinterpret_cast<float2*>(out + (size_t)(row + 8) * OUT_FEAT + col);
            *p0 = make_float2(acc[mi][nj][0], acc[mi][nj][1]);
            *p1 = make_float2(acc[mi][nj][2], acc[mi][nj][3]);
        }
    }
}

// ---------------------------------------------------------------------------
// Launch (2 kernels)
// ---------------------------------------------------------------------------
extern "C" void kernel_launch(void* const* d_in, const int* in_sizes, int n_in,
                              void* d_out, int out_size) {
    (void)in_sizes; (void)n_in; (void)out_size;
    const float* x    = (const float*)d_in[0];   // [2048, 4096] fp32
    const float* w    = (const float*)d_in[1];   // [2048, 32, 32] fp32
    const int*   rows = (const int*)d_in[2];     // [2048] int32
    const int*   cols = (const int*)d_in[3];     // [2048] int32
    float*       out  = (float*)d_out;           // [2048, 4096] fp32

    cvt_csr_kernel<<<X_F4_BLOCKS + W_F4_BLOCKS + 1, 256>>>(x, w, rows, cols);

    dim3 grid(N_ROW_BLOCKS, N_BATCH_TILES);
    bsd_main_kernel<<<grid, CTA_THREADS>>>(out);
}

// round 14
// speedup vs baseline: 1.1090x; 1.0812x over previous
#include <cuda_runtime.h>
#include <cuda_fp16.h>
#include <cstdint>

// ---------------------------------------------------------------------------
// Problem constants
// ---------------------------------------------------------------------------
#define BATCH        2048
#define IN_FEAT      4096
#define OUT_FEAT     4096
#define BLOCK        32
#define NNZ          2048
#define N_ROW_BLOCKS 128
#define MTILE        128                    // batch rows per work item (2 warps x 64)
#define N_BATCH_TILES (BATCH / MTILE)       // 16
#define N_ITEMS      (N_ROW_BLOCKS * N_BATCH_TILES)   // 2048
#define N_CHUNKS     (NNZ / 32)             // 64

// ---------------------------------------------------------------------------
// Device scratch (__device__ globals only; no runtime allocation)
// ---------------------------------------------------------------------------
__device__ __align__(256) __half g_xh[BATCH * IN_FEAT];     // 16 MB
__device__ __align__(256) __half g_wh[NNZ * BLOCK * BLOCK]; // 4 MB
__device__ int g_hist[N_CHUNKS * N_ROW_BLOCKS];   // per-chunk row histogram
__device__ int g_base[N_CHUNKS * N_ROW_BLOCKS];   // per-chunk scatter bases
__device__ int g_cnt[N_ROW_BLOCKS];
__device__ int g_off[N_ROW_BLOCKS];
__device__ int g_order[N_ROW_BLOCKS];   // row-blocks sorted by cnt desc
__device__ int g_list[NNZ];             // packed: (col << 16) | nnz_index
__device__ int g_wctr;                  // persistent-kernel work counter

// ---------------------------------------------------------------------------
// Helpers
// ---------------------------------------------------------------------------
__device__ __forceinline__ uint32_t smem_u32(const void* p) {
    uint32_t a;
    asm("{ .reg .u64 t; cvta.to.shared.u64 t, %1; cvt.u32.u64 %0, t; }"
        : "=r"(a) : "l"(p));
    return a;
}

// SW64 swizzle for 64B-pitch rows: XOR bits [5:4] with bits [9:8].
#define SW64(o) ((o) ^ (((o) >> 3) & 0x30))

#define CP_ASYNC16(dst, src) \
    asm volatile("cp.async.cg.shared.global [%0], [%1], 16;" \
                 :: "r"(dst), "l"(src) : "memory")
#define CP_COMMIT() asm volatile("cp.async.commit_group;" ::: "memory")
#define CP_WAIT1()  asm volatile("cp.async.wait_group 1;" ::: "memory")

__device__ __forceinline__ void ldsm_x4(uint32_t* r, uint32_t addr) {
    asm volatile("ldmatrix.sync.aligned.m8n8.x4.shared.b16 {%0,%1,%2,%3}, [%4];"
                 : "=r"(r[0]), "=r"(r[1]), "=r"(r[2]), "=r"(r[3])
                 : "r"(addr));
}

__device__ __forceinline__ void mma_16816(float* d, const uint32_t* a,
                                          const uint32_t* b) {
    asm volatile(
        "mma.sync.aligned.m16n8k16.row.col.f32.f16.f16.f32 "
        "{%0,%1,%2,%3}, {%4,%5,%6,%7}, {%8,%9}, {%0,%1,%2,%3};"
        : "+f"(d[0]), "+f"(d[1]), "+f"(d[2]), "+f"(d[3])
        : "r"(a[0]), "r"(a[1]), "r"(a[2]), "r"(a[3]), "r"(b[0]), "r"(b[1]));
}

// ---------------------------------------------------------------------------
// Kernel 1: fused fp32->fp16 conversion (x, w) + complete CSR build.
// Grid: 8192 x-blocks + 2048 w-blocks + 1 CSR block, 256 threads each.
// Also resets the work counter every launch (graph-replay determinism).
// ---------------------------------------------------------------------------
#define X_F4_BLOCKS 8192
#define W_F4_BLOCKS 2048

__device__ __forceinline__ void csr_build_block(const int* __restrict__ rows,
                                                const int* __restrict__ cols) {
    const int t   = threadIdx.x;           // 0..255
    const int wrp = t >> 5;                // 0..7
    const int lid = t & 31;

    if (t == 0) g_wctr = 0;                // reset work counter for main kernel

    // ---- phase 0: zero histogram (8192 ints, 32 per thread) ----
#pragma unroll
    for (int i = 0; i < 32; i++) g_hist[i * 256 + t] = 0;
    __syncthreads();

    // ---- phase 1: per-chunk histogram via match_any (8 chunks per warp) ----
#pragma unroll
    for (int p = 0; p < 8; p++) {
        int c = p * 8 + wrp;               // chunk 0..63
        int n = c * 32 + lid;
        int row = rows[n];
        unsigned m = __match_any_sync(0xffffffffu, row);
        int rank = __popc(m & ((1u << lid) - 1));
        if (rank == 0) g_hist[c * N_ROW_BLOCKS + row] = __popc(m);
    }
    __syncthreads();

    // ---- phase 2: totals, offsets, longest-first order, chunk bases ----
    if (t < N_ROW_BLOCKS) {
        int sum = 0;
#pragma unroll 8
        for (int c = 0; c < N_CHUNKS; c++) sum += g_hist[c * N_ROW_BLOCKS + t];
        g_cnt[t] = sum;
    }
    __syncthreads();
    if (t < N_ROW_BLOCKS) {
        const int cnt = g_cnt[t];
        int off = 0, rank = 0;
#pragma unroll 8
        for (int i = 0; i < N_ROW_BLOCKS; i++) {
            int ci = g_cnt[i];
            off  += (i < t) ? ci : 0;
            rank += (ci > cnt) || (ci == cnt && i < t);
        }
        g_off[t] = off;
        g_order[rank] = t;
        int run = off;
#pragma unroll 8
        for (int c = 0; c < N_CHUNKS; c++) {
            g_base[c * N_ROW_BLOCKS + t] = run;
            run += g_hist[c * N_ROW_BLOCKS + t];
        }
    }
    __syncthreads();

    // ---- phase 3: scatter (chunk = pass*8 + warp, lane order == n order) ----
#pragma unroll
    for (int p = 0; p < 8; p++) {
        int n = p * 256 + t;
        int row = rows[n];
        int chunk = n >> 5;                // == p*8 + wrp
        unsigned m = __match_any_sync(0xffffffffu, row);
        int rank = __popc(m & ((1u << lid) - 1));
        g_list[g_base[chunk * N_ROW_BLOCKS + row] + rank] = (cols[n] << 16) | n;
    }
}

__global__ void __launch_bounds__(256)
cvt_csr_kernel(const float* __restrict__ x, const float* __restrict__ w,
               const int* __restrict__ rows, const int* __restrict__ cols) {
    int b = blockIdx.x;
    if (b < X_F4_BLOCKS) {
        int i = b * 256 + threadIdx.x;
        float4 v = reinterpret_cast<const float4*>(x)[i];
        __half2* d = reinterpret_cast<__half2*>(g_xh);
        d[2 * i]     = __floats2half2_rn(v.x, v.y);
        d[2 * i + 1] = __floats2half2_rn(v.z, v.w);
    } else if (b < X_F4_BLOCKS + W_F4_BLOCKS) {
        int i = (b - X_F4_BLOCKS) * 256 + threadIdx.x;
        float4 v = reinterpret_cast<const float4*>(w)[i];
        __half2* d = reinterpret_cast<__half2*>(g_wh);
        d[2 * i]     = __floats2half2_rn(v.x, v.y);
        d[2 * i + 1] = __floats2half2_rn(v.z, v.w);
    } else {
        csr_build_block(rows, cols);
    }
}

// ---------------------------------------------------------------------------
// Kernel 2: PERSISTENT block-sparse GEMM, warp tile 64x32 (R10 inner loop).
// Grid 148*7 CTAs x 64 threads; items pulled via atomicAdd in longest-first
// order: item i -> rank i>>4 (row block via g_order), bt i&15. Output tiles
// are disjoint, so processing order does not affect results (deterministic).
// 3 stages x 10KB static SMEM, wait_group 1, one barrier per block + one
// barrier per item (guards stage reuse across items).
// ---------------------------------------------------------------------------
#define A_BYTES     (MTILE * 64)           // 8192 per stage
#define B_BYTES     (BLOCK * 64)           // 2048 per stage
#define STAGE_BYTES (A_BYTES + B_BYTES)    // 10240
#define STAGES      3
#define CTA_THREADS 64
#define GRID_MAIN   (148 * 7)

__device__ __forceinline__ void issue_loads(uint32_t sA, uint32_t sB,
                                            int tid, int batch0, int packed) {
    const int c   = packed >> 16;
    const int idx = packed & 0xffff;
    // A: 128 rows x 4 segs = 512 x 16B ops over 64 threads (8 each).
#pragma unroll
    for (int i = 0; i < 8; i++) {
        int f = i * 64 + tid;
        int row = f >> 2, seg = f & 3;
        const char* src = reinterpret_cast<const char*>(
            g_xh + (size_t)(batch0 + row) * IN_FEAT + c * BLOCK + seg * 8);
        CP_ASYNC16(sA + SW64((uint32_t)row * 64 + seg * 16), src);
    }
    // B: 32 rows x 4 segs = 128 x 16B ops over 64 threads (2 each).
#pragma unroll
    for (int i = 0; i < 2; i++) {
        int f = i * 64 + tid;
        int wr = f >> 2, wi = f & 3;
        const char* src = reinterpret_cast<const char*>(
            g_wh + (size_t)idx * (BLOCK * BLOCK) + wr * BLOCK + wi * 8);
        CP_ASYNC16(sB + SW64((uint32_t)wr * 64 + wi * 16), src);
    }
}

__global__ void __launch_bounds__(CTA_THREADS)
bsd_main_kernel(float* __restrict__ out) {
    __shared__ __align__(1024) char sbuf[STAGES * STAGE_BYTES];   // 30720 B
    __shared__ int s_item;

    const int tid = threadIdx.x;
    const int wid = tid >> 5;          // 0..1
    const int lid = tid & 31;
    const int mbase = wid * 64;        // warp owns 64 batch rows

    const uint32_t sb = smem_u32(sbuf);

    for (;;) {
        // ---- grab next work item; barrier also guards stage-buffer reuse ----
        if (tid == 0) s_item = atomicAdd(&g_wctr, 1);
        __syncthreads();
        const int item = s_item;
        if (item >= N_ITEMS) break;

        const int r      = g_order[item >> 4];
        const int batch0 = (item & 15) * MTILE;
        const int cnt = g_cnt[r];
        const int off = g_off[r];

        float acc[4][4][4];
#pragma unroll
        for (int mi = 0; mi < 4; mi++)
#pragma unroll
            for (int nj = 0; nj < 4; nj++)
#pragma unroll
                for (int k = 0; k < 4; k++) acc[mi][nj][k] = 0.f;

        // Prologue: issue blocks 0 and 1 into stages 0 and 1 (commit always).
        if (cnt > 0) issue_loads(sb, sb + A_BYTES, tid, batch0, g_list[off]);
        CP_COMMIT();
        if (cnt > 1) issue_loads(sb + STAGE_BYTES, sb + STAGE_BYTES + A_BYTES,
                                 tid, batch0, g_list[off + 1]);
        CP_COMMIT();

        // Mainloop, one barrier per iteration (R10 scheme).
        for (int it = 0; it < cnt; ++it) {
            CP_WAIT1();
            __syncthreads();

            const int j = it + STAGES - 1;
            const uint32_t sw = sb + ((uint32_t)(j % STAGES)) * STAGE_BYTES;
            if (j < cnt)
                issue_loads(sw, sw + A_BYTES, tid, batch0, g_list[off + j]);
            CP_COMMIT();

            const uint32_t sA = sb + ((uint32_t)(it % STAGES)) * STAGE_BYTES;
            const uint32_t sB = sA + A_BYTES;

            // B fragments once per iteration (shared across 4 mi sub-tiles).
            uint32_t bf[2][4][2];
#pragma unroll
            for (int ki = 0; ki < 2; ki++)
#pragma unroll
                for (int p = 0; p < 2; p++) {
                    uint32_t n  = (uint32_t)(p * 16 + ((lid >> 4) * 8) + (lid & 7));
                    uint32_t kb = (uint32_t)(ki * 32 + (((lid >> 3) & 1) * 16));
                    uint32_t tt[4];
                    ldsm_x4(tt, sB + SW64(n * 64 + kb));
                    bf[ki][2 * p + 0][0] = tt[0];
                    bf[ki][2 * p + 0][1] = tt[1];
                    bf[ki][2 * p + 1][0] = tt[2];
                    bf[ki][2 * p + 1][1] = tt[3];
                }

            // A fragments loaded per mi (keeps only 8 af regs live).
#pragma unroll
            for (int mi = 0; mi < 4; mi++) {
                uint32_t af[2][4];
#pragma unroll
                for (int ki = 0; ki < 2; ki++) {
                    uint32_t row = (uint32_t)(mbase + mi * 16 + (lid & 15));
                    uint32_t kb  = (uint32_t)(ki * 32 + ((lid >> 4) * 16));
                    ldsm_x4(af[ki], sA + SW64(row * 64 + kb));
                }
#pragma unroll
                for (int nj = 0; nj < 4; nj++)
#pragma unroll
                    for (int ki = 0; ki < 2; ki++)
                        mma_16816(acc[mi][nj], af[ki], bf[ki][nj]);
            }
        }

        // Epilogue: D fragment layout -> global (zeros if row-block empty).
        const int g = lid >> 2, t4 = lid & 3;
#pragma unroll
        for (int mi = 0; mi < 4; mi++) {
#pragma unroll
            for (int nj = 0; nj < 4; nj++) {
                const int row = batch0 + mbase + mi * 16 + g;
                const int col = r * BLOCK + nj * 8 + 2 * t4;
                float2* p0 = reinterpret_cast<float2*>(out + (size_t)row * OUT_FEAT + col);
                float2* p1 = reinterpret_cast<float2*>(out + (size_t)(row + 8) * OUT_FEAT + col);
                *p0 = make_float2(acc[mi][nj][0], acc[mi][nj][1]);
                *p1 = make_float2(acc[mi][nj][2], acc[mi][nj][3]);
            }
        }
    }
}

// ---------------------------------------------------------------------------
// Launch (2 kernels)
// ---------------------------------------------------------------------------
extern "C" void kernel_launch(void* const* d_in, const int* in_sizes, int n_in,
                              void* d_out, int out_size) {
    (void)in_sizes; (void)n_in; (void)out_size;
    const float* x    = (const float*)d_in[0];   // [2048, 4096] fp32
    const float* w    = (const float*)d_in[1];   // [2048, 32, 32] fp32
    const int*   rows = (const int*)d_in[2];     // [2048] int32
    const int*   cols = (const int*)d_in[3];     // [2048] int32
    float*       out  = (float*)d_out;           // [2048, 4096] fp32

    cvt_csr_kernel<<<X_F4_BLOCKS + W_F4_BLOCKS + 1, 256>>>(x, w, rows, cols);

    bsd_main_kernel<<<GRID_MAIN, CTA_THREADS>>>(out);
}